// round 5
// baseline (speedup 1.0000x reference)
#include <cuda_runtime.h>
#include <math.h>
#include <stdint.h>

#define N_TOKENS 16384
#define D_MODEL  4096
#define N_EXP    64
#define LB_COEF  0.01f

#define KC     32
#define NCHUNK (D_MODEL / KC)     // 128
#define TM     128
#define NCTA   (N_TOKENS / TM)    // 128
#define NTHR   256

// smem stage layout (float indices). Each row stores 32 k-values as
// interleaved [hi,lo] pairs = 64 floats, padded to pitch 72.
#define PITCH   72
#define B_F     (128 * PITCH)               // B region after 128 A rows
#define STAGE_F ((128 + 64) * PITCH)        // 13824 floats per stage
#define DYN_BYTES (2 * STAGE_F * 4)         // 110592 bytes

// ---------------- helpers ----------------
static __device__ __forceinline__ uint32_t tf32_of(float f) {
    uint32_t r;
    asm("cvt.rna.tf32.f32 %0, %1;" : "=r"(r) : "f"(f));
    return r;
}

// convert float4 -> two uint4 of interleaved {hi,lo} pairs
static __device__ __forceinline__ void cvt4i(float4 v, uint4& q0, uint4& q1) {
    uint32_t hx = tf32_of(v.x), hy = tf32_of(v.y), hz = tf32_of(v.z), hw = tf32_of(v.w);
    q0.x = hx; q0.y = tf32_of(v.x - __uint_as_float(hx));
    q0.z = hy; q0.w = tf32_of(v.y - __uint_as_float(hy));
    q1.x = hz; q1.y = tf32_of(v.z - __uint_as_float(hz));
    q1.z = hw; q1.w = tf32_of(v.w - __uint_as_float(hw));
}

#define MMA(d, a, b)                                                     \
    asm volatile(                                                        \
        "mma.sync.aligned.m16n8k8.row.col.f32.tf32.tf32.f32 "            \
        "{%0,%1,%2,%3}, {%4,%5,%6,%7}, {%8,%9}, {%0,%1,%2,%3};"          \
        : "+f"((d)[0]), "+f"((d)[1]), "+f"((d)[2]), "+f"((d)[3])         \
        : "r"((a)[0]), "r"((a)[1]), "r"((a)[2]), "r"((a)[3]),            \
          "r"((b)[0]), "r"((b)[1]))

// ---------------- device scratch (zero-initialized at module load) ----------------
__device__ float g_psum[N_EXP];
__device__ int   g_cnt[N_EXP];
__device__ int   g_ticket;

// ---------------- fused GEMM (3xTF32 mma.sync) + softmax/top2 + loss ----------------
// 256 threads = 8 warps; CTA tile 128 tokens x 64 experts; warp tile 32x32.
__global__ __launch_bounds__(NTHR, 1)
void router_kernel(const float* __restrict__ x,
                   const float* __restrict__ gw,
                   float* __restrict__ out)
{
    extern __shared__ float dynsm[];
    __shared__ int   cb[N_EXP];
    __shared__ float s_red[N_EXP];
    __shared__ int   s_islast;

    const int tid  = threadIdx.x;
    const int t0   = blockIdx.x * TM;
    const int lane = tid & 31;
    const int wid  = tid >> 5;
    const int wm   = wid >> 1;          // 0..3  -> token base wm*32
    const int wn   = wid & 1;           // 0..1  -> expert base wn*32
    const int lr   = lane >> 2;         // groupID
    const int lc   = lane & 3;          // threadID_in_group

    uint32_t* sm = (uint32_t*)dynsm;

    if (tid < N_EXP) cb[tid] = 0;

    // fill mapping: thread -> (row block R, float4 col g)
    const int R = tid >> 3;             // 0..31
    const int g = tid & 7;              // 0..7

    const float4* x4 = (const float4*)x;     // row pitch 1024 float4
    const float4* w4 = (const float4*)gw;    // row pitch 1024 float4

    size_t xoff[4], woff[2];
#pragma unroll
    for (int k = 0; k < 4; k++) xoff[k] = (size_t)(t0 + R + 32 * k) * 1024 + g;
#pragma unroll
    for (int k = 0; k < 2; k++) woff[k] = (size_t)(R + 32 * k) * 1024 + g;

    float4 xa[4], wb[2];

    // ---- prologue: load chunk 0, convert, store to stage 0
#pragma unroll
    for (int k = 0; k < 4; k++) xa[k] = x4[xoff[k]];
#pragma unroll
    for (int k = 0; k < 2; k++) wb[k] = w4[woff[k]];
    {
        uint32_t* s = sm;
#pragma unroll
        for (int k = 0; k < 4; k++) {
            uint4 q0, q1; cvt4i(xa[k], q0, q1);
            uint32_t* p = s + (R + 32 * k) * PITCH + 8 * g;
            *(uint4*)p = q0; *(uint4*)(p + 4) = q1;
        }
#pragma unroll
        for (int k = 0; k < 2; k++) {
            uint4 q0, q1; cvt4i(wb[k], q0, q1);
            uint32_t* p = s + B_F + (R + 32 * k) * PITCH + 8 * g;
            *(uint4*)p = q0; *(uint4*)(p + 4) = q1;
        }
    }
    __syncthreads();

    float acc[2][4][4];
#pragma unroll
    for (int mi = 0; mi < 2; mi++)
#pragma unroll
        for (int ni = 0; ni < 4; ni++)
#pragma unroll
            for (int j = 0; j < 4; j++) acc[mi][ni][j] = 0.0f;

    // ---- main loop: double-buffered, one bar per chunk
    for (int c = 0; c < NCHUNK; c++) {
        if (c + 1 < NCHUNK) {
#pragma unroll
            for (int k = 0; k < 4; k++) xa[k] = x4[xoff[k] + (size_t)(c + 1) * 8];
#pragma unroll
            for (int k = 0; k < 2; k++) wb[k] = w4[woff[k] + (size_t)(c + 1) * 8];
        }

        const uint32_t* s = sm + (c & 1) * STAGE_F;
#pragma unroll
        for (int ks = 0; ks < 4; ks++) {
            uint32_t ah[2][4], al[2][4];
#pragma unroll
            for (int mi = 0; mi < 2; mi++) {
                int b0 = (wm * 32 + mi * 16 + lr) * PITCH + 2 * (ks * 8 + lc);
                uint2 p0 = *(const uint2*)(s + b0);                   // k
                uint2 p2 = *(const uint2*)(s + b0 + 8);               // k+4
                uint2 p1 = *(const uint2*)(s + b0 + 8 * PITCH);       // row+8, k
                uint2 p3 = *(const uint2*)(s + b0 + 8 * PITCH + 8);   // row+8, k+4
                ah[mi][0] = p0.x; al[mi][0] = p0.y;
                ah[mi][1] = p1.x; al[mi][1] = p1.y;
                ah[mi][2] = p2.x; al[mi][2] = p2.y;
                ah[mi][3] = p3.x; al[mi][3] = p3.y;
            }
#pragma unroll
            for (int ni = 0; ni < 4; ni++) {
                int b0 = B_F + (wn * 32 + ni * 8 + lr) * PITCH + 2 * (ks * 8 + lc);
                uint2 q0 = *(const uint2*)(s + b0);
                uint2 q1 = *(const uint2*)(s + b0 + 8);
                uint32_t bh[2] = { q0.x, q1.x };
                uint32_t bl[2] = { q0.y, q1.y };
#pragma unroll
                for (int mi = 0; mi < 2; mi++) {
                    MMA(acc[mi][ni], ah[mi], bh);
                    MMA(acc[mi][ni], al[mi], bh);
                    MMA(acc[mi][ni], ah[mi], bl);
                }
            }
        }

        if (c + 1 < NCHUNK) {
            uint32_t* d = sm + ((c + 1) & 1) * STAGE_F;
#pragma unroll
            for (int k = 0; k < 4; k++) {
                uint4 q0, q1; cvt4i(xa[k], q0, q1);
                uint32_t* p = d + (R + 32 * k) * PITCH + 8 * g;
                *(uint4*)p = q0; *(uint4*)(p + 4) = q1;
            }
#pragma unroll
            for (int k = 0; k < 2; k++) {
                uint4 q0, q1; cvt4i(wb[k], q0, q1);
                uint32_t* p = d + B_F + (R + 32 * k) * PITCH + 8 * g;
                *(uint4*)p = q0; *(uint4*)(p + 4) = q1;
            }
        }
        __syncthreads();
    }

    // ---- dump logits to smem G[128][65] (overlays stage 0; all reads done)
    float* G = dynsm;
#pragma unroll
    for (int mi = 0; mi < 2; mi++)
#pragma unroll
        for (int ni = 0; ni < 4; ni++) {
            int tr = wm * 32 + mi * 16 + lr;
            int ec = wn * 32 + ni * 8 + 2 * lc;
            G[tr * 65 + ec]           = acc[mi][ni][0];
            G[tr * 65 + ec + 1]       = acc[mi][ni][1];
            G[(tr + 8) * 65 + ec]     = acc[mi][ni][2];
            G[(tr + 8) * 65 + ec + 1] = acc[mi][ni][3];
        }
    __syncthreads();

    // ---- per-token softmax + top2; write normalized probs back into G
    if (tid < TM) {
        float* row = G + tid * 65;
        float m = row[0];
#pragma unroll 8
        for (int e = 1; e < N_EXP; e++) m = fmaxf(m, row[e]);

        float ssum = 0.0f;
#pragma unroll 8
        for (int e = 0; e < N_EXP; e++) {
            float v = expf(row[e] - m);
            row[e] = v;
            ssum += v;
        }
        float inv = 1.0f / ssum;

        float v1 = -1.0f, v2 = -1.0f;
        int   i1 = 0,     i2 = 0;
#pragma unroll 8
        for (int e = 0; e < N_EXP; e++) {
            float p = row[e] * inv;
            row[e] = p;
            if (p > v1)      { v2 = v1; i2 = i1; v1 = p; i1 = e; }
            else if (p > v2) { v2 = p;  i2 = e; }
        }

        float rn = 1.0f / (v1 + v2);
        int tg = t0 + tid;
        out[2 * tg]     = v1 * rn;
        out[2 * tg + 1] = v2 * rn;
        out[2 * N_TOKENS + 2 * tg]     = (float)i1;
        out[2 * N_TOKENS + 2 * tg + 1] = (float)i2;
        atomicAdd(&cb[i1], 1);
    }
    __syncthreads();

    // ---- per-expert prob sums over this block's tokens -> global
    if (tid < N_EXP) {
        float s = 0.0f;
#pragma unroll 8
        for (int t = 0; t < TM; t++) s += G[t * 65 + tid];
        atomicAdd(&g_psum[tid], s);
        atomicAdd(&g_cnt[tid], cb[tid]);
    }

    // ---- last CTA: loss + scratch reset (deterministic across graph replays)
    if (tid == 0) {
        __threadfence();
        int t = atomicAdd(&g_ticket, 1);
        s_islast = (t == NCTA - 1) ? 1 : 0;
    }
    __syncthreads();
    if (s_islast) {
        __threadfence();
        if (tid < N_EXP) {
            float p = *(volatile float*)&g_psum[tid];
            int   f = *(volatile int*)&g_cnt[tid];
            s_red[tid] = (float)f * p;
            g_psum[tid] = 0.0f;
            g_cnt[tid]  = 0;
        }
        __syncthreads();
        for (int st = 32; st > 0; st >>= 1) {
            if (tid < st) s_red[tid] += s_red[tid + st];
            __syncthreads();
        }
        if (tid == 0) {
            out[4 * N_TOKENS] = LB_COEF * s_red[0] * (1.0f / N_TOKENS) * (1.0f / N_TOKENS);
            g_ticket = 0;
        }
    }
}

// ---------------- launch ----------------
extern "C" void kernel_launch(void* const* d_in, const int* in_sizes, int n_in,
                              void* d_out, int out_size)
{
    const float* x  = (const float*)d_in[0];
    const float* gw = (const float*)d_in[1];
    float* out = (float*)d_out;

    cudaFuncSetAttribute(router_kernel,
                         cudaFuncAttributeMaxDynamicSharedMemorySize, DYN_BYTES);

    router_kernel<<<NCTA, NTHR, DYN_BYTES>>>(x, gw, out);
}

// round 6
// speedup vs baseline: 2.2172x; 2.2172x over previous
#include <cuda_runtime.h>
#include <math.h>
#include <stdint.h>

#define N_TOKENS 16384
#define D_MODEL  4096
#define N_EXP    64
#define LB_COEF  0.01f

#define KC     32
#define NCHUNK (D_MODEL / KC)     // 128
#define TM     128
#define NCTA   (N_TOKENS / TM)    // 128
#define NTHR   512

// smem stage layout (float indices), pitch 36 => conflict-free frag loads
#define PITCH   36
#define A_HI    0
#define A_LO    (128 * PITCH)               // 4608
#define B_HI    (2 * 128 * PITCH)           // 9216
#define B_LO    (B_HI + 64 * PITCH)         // 11520
#define STAGE_F (B_LO + 64 * PITCH)         // 13824 floats per stage
#define DYN_BYTES (2 * STAGE_F * 4)         // 110592 bytes

// ---------------- helpers ----------------
static __device__ __forceinline__ uint32_t tf32_of(float f) {
    uint32_t r;
    asm("cvt.rna.tf32.f32 %0, %1;" : "=r"(r) : "f"(f));
    return r;
}

static __device__ __forceinline__ void cvt4(float4 v, uint4& h, uint4& l) {
    h.x = tf32_of(v.x); h.y = tf32_of(v.y); h.z = tf32_of(v.z); h.w = tf32_of(v.w);
    l.x = tf32_of(v.x - __uint_as_float(h.x));
    l.y = tf32_of(v.y - __uint_as_float(h.y));
    l.z = tf32_of(v.z - __uint_as_float(h.z));
    l.w = tf32_of(v.w - __uint_as_float(h.w));
}

#define MMA(d, a, b)                                                     \
    asm volatile(                                                        \
        "mma.sync.aligned.m16n8k8.row.col.f32.tf32.tf32.f32 "            \
        "{%0,%1,%2,%3}, {%4,%5,%6,%7}, {%8,%9}, {%0,%1,%2,%3};"          \
        : "+f"((d)[0]), "+f"((d)[1]), "+f"((d)[2]), "+f"((d)[3])         \
        : "r"((a)[0]), "r"((a)[1]), "r"((a)[2]), "r"((a)[3]),            \
          "r"((b)[0]), "r"((b)[1]))

// ---------------- device scratch (zero-initialized at module load) ----------------
__device__ float g_psum[N_EXP];
__device__ int   g_cnt[N_EXP];
__device__ int   g_ticket;

// ---------------- fused GEMM (3xTF32 mma.sync) + softmax/top2 + loss ----------------
// 512 threads = 16 warps; CTA tile 128 tokens x 64 experts; warp tile 16x32.
__global__ __launch_bounds__(NTHR, 1)
void router_kernel(const float* __restrict__ x,
                   const float* __restrict__ gw,
                   float* __restrict__ out)
{
    extern __shared__ float dynsm[];
    __shared__ int   cb[N_EXP];
    __shared__ float s_red[N_EXP];
    __shared__ int   s_islast;

    const int tid  = threadIdx.x;
    const int t0   = blockIdx.x * TM;
    const int lane = tid & 31;
    const int wid  = tid >> 5;
    const int wm   = wid >> 1;          // 0..7  -> token base wm*16
    const int wn   = wid & 1;           // 0..1  -> expert base wn*32
    const int lr   = lane >> 2;         // groupID
    const int lc   = lane & 3;          // threadID_in_group

    uint32_t* sm = (uint32_t*)dynsm;

    if (tid < N_EXP) cb[tid] = 0;

    // fill mapping: thread -> rows {R (A), R+64 (A), R (B)}, float4 col g
    const int R = tid >> 3;             // 0..63
    const int g = tid & 7;              // 0..7

    const float4* x4 = (const float4*)x;     // row pitch 1024 float4
    const float4* w4 = (const float4*)gw;    // row pitch 1024 float4

    const size_t xoff0 = (size_t)(t0 + R)      * 1024 + g;
    const size_t xoff1 = (size_t)(t0 + R + 64) * 1024 + g;
    const size_t woff  = (size_t)R             * 1024 + g;

    float4 pa0, pa1, pw;

    // ---- prologue: load chunk 0, convert, store to stage 0
    pa0 = x4[xoff0]; pa1 = x4[xoff1]; pw = w4[woff];
    {
        uint32_t* s = sm;
        uint4 h, l;
        cvt4(pa0, h, l);
        *(uint4*)(s + A_HI + R * PITCH + 4 * g) = h;
        *(uint4*)(s + A_LO + R * PITCH + 4 * g) = l;
        cvt4(pa1, h, l);
        *(uint4*)(s + A_HI + (R + 64) * PITCH + 4 * g) = h;
        *(uint4*)(s + A_LO + (R + 64) * PITCH + 4 * g) = l;
        cvt4(pw, h, l);
        *(uint4*)(s + B_HI + R * PITCH + 4 * g) = h;
        *(uint4*)(s + B_LO + R * PITCH + 4 * g) = l;
    }
    __syncthreads();

    float acc[4][4];
#pragma unroll
    for (int ni = 0; ni < 4; ni++)
#pragma unroll
        for (int j = 0; j < 4; j++) acc[ni][j] = 0.0f;

    // ---- main loop: double-buffered, one bar per chunk
    for (int c = 0; c < NCHUNK; c++) {
        if (c + 1 < NCHUNK) {
            pa0 = x4[xoff0 + (size_t)(c + 1) * 8];
            pa1 = x4[xoff1 + (size_t)(c + 1) * 8];
            pw  = w4[woff  + (size_t)(c + 1) * 8];
        }

        const uint32_t* s = sm + (c & 1) * STAGE_F;
#pragma unroll
        for (int ks = 0; ks < 4; ks++) {
            uint32_t ah[4], al[4];
            {
                int base = (wm * 16 + lr) * PITCH + ks * 8 + lc;
                ah[0] = s[A_HI + base];
                ah[1] = s[A_HI + base + 8 * PITCH];
                ah[2] = s[A_HI + base + 4];
                ah[3] = s[A_HI + base + 8 * PITCH + 4];
                al[0] = s[A_LO + base];
                al[1] = s[A_LO + base + 8 * PITCH];
                al[2] = s[A_LO + base + 4];
                al[3] = s[A_LO + base + 8 * PITCH + 4];
            }
#pragma unroll
            for (int ni = 0; ni < 4; ni++) {
                int bb = (wn * 32 + ni * 8 + lr) * PITCH + ks * 8 + lc;
                uint32_t bh[2] = { s[B_HI + bb], s[B_HI + bb + 4] };
                uint32_t bl[2] = { s[B_LO + bb], s[B_LO + bb + 4] };
                MMA(acc[ni], ah, bh);
                MMA(acc[ni], al, bh);
                MMA(acc[ni], ah, bl);
            }
        }

        if (c + 1 < NCHUNK) {
            uint32_t* d = sm + ((c + 1) & 1) * STAGE_F;
            uint4 h, l;
            cvt4(pa0, h, l);
            *(uint4*)(d + A_HI + R * PITCH + 4 * g) = h;
            *(uint4*)(d + A_LO + R * PITCH + 4 * g) = l;
            cvt4(pa1, h, l);
            *(uint4*)(d + A_HI + (R + 64) * PITCH + 4 * g) = h;
            *(uint4*)(d + A_LO + (R + 64) * PITCH + 4 * g) = l;
            cvt4(pw, h, l);
            *(uint4*)(d + B_HI + R * PITCH + 4 * g) = h;
            *(uint4*)(d + B_LO + R * PITCH + 4 * g) = l;
        }
        __syncthreads();
    }

    // ---- dump logits to smem G[128][65] (overlays stage 0; all reads done)
    float* G = dynsm;
#pragma unroll
    for (int ni = 0; ni < 4; ni++) {
        int tr = wm * 16 + lr;
        int ec = wn * 32 + ni * 8 + 2 * lc;
        G[tr * 65 + ec]           = acc[ni][0];
        G[tr * 65 + ec + 1]       = acc[ni][1];
        G[(tr + 8) * 65 + ec]     = acc[ni][2];
        G[(tr + 8) * 65 + ec + 1] = acc[ni][3];
    }
    __syncthreads();

    // ---- per-token softmax + top2; write normalized probs back into G
    if (tid < TM) {
        float* row = G + tid * 65;
        float m = row[0];
#pragma unroll 8
        for (int e = 1; e < N_EXP; e++) m = fmaxf(m, row[e]);

        float ssum = 0.0f;
#pragma unroll 8
        for (int e = 0; e < N_EXP; e++) {
            float v = expf(row[e] - m);
            row[e] = v;
            ssum += v;
        }
        float inv = 1.0f / ssum;

        float v1 = -1.0f, v2 = -1.0f;
        int   i1 = 0,     i2 = 0;
#pragma unroll 8
        for (int e = 0; e < N_EXP; e++) {
            float p = row[e] * inv;
            row[e] = p;
            if (p > v1)      { v2 = v1; i2 = i1; v1 = p; i1 = e; }
            else if (p > v2) { v2 = p;  i2 = e; }
        }

        float rn = 1.0f / (v1 + v2);
        int tg = t0 + tid;
        out[2 * tg]     = v1 * rn;
        out[2 * tg + 1] = v2 * rn;
        out[2 * N_TOKENS + 2 * tg]     = (float)i1;
        out[2 * N_TOKENS + 2 * tg + 1] = (float)i2;
        atomicAdd(&cb[i1], 1);
    }
    __syncthreads();

    // ---- per-expert prob sums over this block's tokens -> global
    if (tid < N_EXP) {
        float s = 0.0f;
#pragma unroll 8
        for (int t = 0; t < TM; t++) s += G[t * 65 + tid];
        atomicAdd(&g_psum[tid], s);
        atomicAdd(&g_cnt[tid], cb[tid]);
    }

    // ---- last CTA: loss + scratch reset (deterministic across graph replays)
    if (tid == 0) {
        __threadfence();
        int t = atomicAdd(&g_ticket, 1);
        s_islast = (t == NCTA - 1) ? 1 : 0;
    }
    __syncthreads();
    if (s_islast) {
        __threadfence();
        if (tid < N_EXP) {
            float p = *(volatile float*)&g_psum[tid];
            int   f = *(volatile int*)&g_cnt[tid];
            s_red[tid] = (float)f * p;
            g_psum[tid] = 0.0f;
            g_cnt[tid]  = 0;
        }
        __syncthreads();
        for (int st = 32; st > 0; st >>= 1) {
            if (tid < st) s_red[tid] += s_red[tid + st];
            __syncthreads();
        }
        if (tid == 0) {
            out[4 * N_TOKENS] = LB_COEF * s_red[0] * (1.0f / N_TOKENS) * (1.0f / N_TOKENS);
            g_ticket = 0;
        }
    }
}

// ---------------- launch ----------------
extern "C" void kernel_launch(void* const* d_in, const int* in_sizes, int n_in,
                              void* d_out, int out_size)
{
    const float* x  = (const float*)d_in[0];
    const float* gw = (const float*)d_in[1];
    float* out = (float*)d_out;

    cudaFuncSetAttribute(router_kernel,
                         cudaFuncAttributeMaxDynamicSharedMemorySize, DYN_BYTES);

    router_kernel<<<NCTA, NTHR, DYN_BYTES>>>(x, gw, out);
}